// round 13
// baseline (speedup 1.0000x reference)
#include <cuda_runtime.h>
#include <cstdint>
#include <math.h>

// Problem shape (fixed): T=512, B=64, I=H=1024.
#define TSTEPS 512
#define BB     64
#define HH     1024
#define NBH    65536   // B*H
#define NBLK   128     // persistent-kernel blocks (<=148 SMs -> all resident)

// ---------------- output layout (floats) ----------------
// tuple order: spikes[513,B,H], preds[512,B,H], probs[512,B,H], prob_T[B,H], spike_T[B,H]
static const size_t OFF_SPIKES = 0;
static const size_t OFF_PREDS  = (size_t)513 * NBH;
static const size_t OFF_PROBS  = OFF_PREDS + (size_t)TSTEPS * NBH;
static const size_t OFF_PROBT  = OFF_PROBS + (size_t)TSTEPS * NBH;
static const size_t OFF_SPIKET = OFF_PROBT + NBH;

// ---------------- device scratch (static: no allocation) ----------------
static __device__ float g_preXW[(size_t)TSTEPS * NBH];  // 128 MB: x_t @ W_ih for all t
static __device__ float g_preHH[NBH];                   // spike @ W_hh (full-K serial)
static __device__ float g_prob[NBH];                    // carry: prob_{t-1}
static __device__ float g_spike[NBH];                   // carry: spike_{t-1}
static __device__ unsigned g_bar;                       // grid barrier arrive counter

// ---------------- threefry2x32 (JAX-exact, 20 rounds) ----------------
__host__ __device__ inline void tf2x32(unsigned k0, unsigned k1,
                                       unsigned x0, unsigned x1,
                                       unsigned& o0, unsigned& o1) {
  unsigned ks2 = k0 ^ k1 ^ 0x1BD11BDAu;
  x0 += k0; x1 += k1;
#define TFR(r) { x0 += x1; x1 = (x1 << (r)) | (x1 >> (32 - (r))); x1 ^= x0; }
  TFR(13) TFR(15) TFR(26) TFR(6)
  x0 += k1;  x1 += ks2 + 1u;
  TFR(17) TFR(29) TFR(16) TFR(24)
  x0 += ks2; x1 += k0 + 2u;
  TFR(13) TFR(15) TFR(26) TFR(6)
  x0 += k0;  x1 += k1 + 3u;
  TFR(17) TFR(29) TFR(16) TFR(24)
  x0 += k1;  x1 += ks2 + 4u;
  TFR(13) TFR(15) TFR(26) TFR(6)
  x0 += ks2; x1 += k0 + 5u;
#undef TFR
  o0 = x0; o1 = x1;
}

// ---------------- bit-faithful replica of libdevice __nv_expf ----------------
// j = rint(a*log2e) via the 1.5*2^23 magic-number trick; Cody-Waite reduction
// with ln2_hi = 6.93145752e-1 (0x3F317200), ln2_lo = 1.42860677e-6; degree-6
// FMA polynomial; exact power-of-two scaling. All ops are explicit *_rn
// intrinsics so compiler fast-math flags cannot perturb them.
__device__ inline float expf_ref(float a) {
  float j = __fadd_rn(__fmaf_rn(a, 1.442695f, 12582912.0f), -12582912.0f);
  int   i = (int)j;
  float f = __fmaf_rn(j, -6.93145752e-1f, a);
  f = __fmaf_rn(j, -1.42860677e-6f, f);
  float r =                 1.37805939e-3f;
  r = __fmaf_rn(r, f, 8.37312452e-3f);
  r = __fmaf_rn(r, f, 4.16695364e-2f);
  r = __fmaf_rn(r, f, 1.66664720e-1f);
  r = __fmaf_rn(r, f, 4.99999851e-1f);
  r = __fmaf_rn(r, f, 1.00000000e+0f);
  r = __fmaf_rn(r, f, 1.00000000e+0f);
  // scale by 2^i in two exact power-of-two multiplies (robust for |i| up to ~250)
  int ih = i / 2;
  r = __fmul_rn(r, __int_as_float((unsigned)(ih + 127) << 23));
  r = __fmul_rn(r, __int_as_float((unsigned)(i - ih + 127) << 23));
  return r;
}

// XLA LogisticExpander form: logistic(x) = 1 / (1 + exp(-x))
__device__ inline float sigmoid_ref(float x) {
  float e = expf_ref(-x);
  return __fdiv_rn(1.0f, __fadd_rn(1.0f, e));
}

// ---------------- init: zero carries, spikes[0], barrier ----------------
__global__ __launch_bounds__(256) void init_kernel(float* __restrict__ out) {
  int i = blockIdx.x * 256 + threadIdx.x;   // 65536 threads
  g_prob[i]  = 0.0f;
  g_spike[i] = 0.0f;
  out[OFF_SPIKES + i] = 0.0f;               // spikes[0] = 0
  if (i == 0) g_bar = 0u;
}

// ---------------- big SGEMM: g_preXW = X @ W_ih (serial-K per element) -------
__global__ __launch_bounds__(256) void sgemm_xw(const float* __restrict__ A,
                                                const float* __restrict__ B) {
  const int n0 = blockIdx.x * 128;
  const int m0 = blockIdx.y * 128;
  __shared__ float As[8][128];
  __shared__ float Bs[8][128];
  const int tid = threadIdx.x;
  const int tx = tid & 15, ty = tid >> 4;
  float acc[8][8];
#pragma unroll
  for (int i = 0; i < 8; i++)
#pragma unroll
    for (int j = 0; j < 8; j++) acc[i][j] = 0.0f;

  for (int k0 = 0; k0 < 1024; k0 += 8) {
    {
      int r = tid >> 1, kq = tid & 1;
      float4 v = *(const float4*)(A + (size_t)(m0 + r) * 1024 + k0 + kq * 4);
      As[kq * 4 + 0][r] = v.x; As[kq * 4 + 1][r] = v.y;
      As[kq * 4 + 2][r] = v.z; As[kq * 4 + 3][r] = v.w;
    }
    {
      int r = tid >> 5, c = (tid & 31) * 4;
      *(float4*)&Bs[r][c] = *(const float4*)(B + (size_t)(k0 + r) * 1024 + n0 + c);
    }
    __syncthreads();
#pragma unroll
    for (int kk = 0; kk < 8; kk++) {
      float a[8], b[8];
      *(float4*)&a[0] = *(float4*)&As[kk][ty * 8];
      *(float4*)&a[4] = *(float4*)&As[kk][ty * 8 + 4];
      *(float4*)&b[0] = *(float4*)&Bs[kk][tx * 8];
      *(float4*)&b[4] = *(float4*)&Bs[kk][tx * 8 + 4];
#pragma unroll
      for (int i = 0; i < 8; i++)
#pragma unroll
        for (int j = 0; j < 8; j++)
          acc[i][j] = __fmaf_rn(a[i], b[j], acc[i][j]);
    }
    __syncthreads();
  }
#pragma unroll
  for (int i = 0; i < 8; i++) {
    float* crow = g_preXW + (size_t)(m0 + ty * 8 + i) * 1024 + n0 + tx * 8;
    *(float4*)(crow)     = make_float4(acc[i][0], acc[i][1], acc[i][2], acc[i][3]);
    *(float4*)(crow + 4) = make_float4(acc[i][4], acc[i][5], acc[i][6], acc[i][7]);
  }
}

// ---------------- big SGEMM: preds = sigmoid_ref(probs @ W_hh^T) -------------
__global__ __launch_bounds__(256) void sgemm_pred(const float* __restrict__ A,
                                                  const float* __restrict__ W,
                                                  float* __restrict__ C) {
  const int n0 = blockIdx.x * 128;
  const int m0 = blockIdx.y * 128;
  __shared__ float As[8][128];
  __shared__ float Bs[8][128];
  const int tid = threadIdx.x;
  const int tx = tid & 15, ty = tid >> 4;
  float acc[8][8];
#pragma unroll
  for (int i = 0; i < 8; i++)
#pragma unroll
    for (int j = 0; j < 8; j++) acc[i][j] = 0.0f;

  for (int k0 = 0; k0 < 1024; k0 += 8) {
    {
      int r = tid >> 1, kq = tid & 1;
      float4 v = *(const float4*)(A + (size_t)(m0 + r) * 1024 + k0 + kq * 4);
      As[kq * 4 + 0][r] = v.x; As[kq * 4 + 1][r] = v.y;
      As[kq * 4 + 2][r] = v.z; As[kq * 4 + 3][r] = v.w;
    }
    {
      // B = W^T: Bs[k][n] = W[n0+n][k0+k]
      int r = tid >> 1, kq = tid & 1;
      float4 v = *(const float4*)(W + (size_t)(n0 + r) * 1024 + k0 + kq * 4);
      Bs[kq * 4 + 0][r] = v.x; Bs[kq * 4 + 1][r] = v.y;
      Bs[kq * 4 + 2][r] = v.z; Bs[kq * 4 + 3][r] = v.w;
    }
    __syncthreads();
#pragma unroll
    for (int kk = 0; kk < 8; kk++) {
      float a[8], b[8];
      *(float4*)&a[0] = *(float4*)&As[kk][ty * 8];
      *(float4*)&a[4] = *(float4*)&As[kk][ty * 8 + 4];
      *(float4*)&b[0] = *(float4*)&Bs[kk][tx * 8];
      *(float4*)&b[4] = *(float4*)&Bs[kk][tx * 8 + 4];
#pragma unroll
      for (int i = 0; i < 8; i++)
#pragma unroll
        for (int j = 0; j < 8; j++)
          acc[i][j] = __fmaf_rn(a[i], b[j], acc[i][j]);
    }
    __syncthreads();
  }
#pragma unroll
  for (int i = 0; i < 8; i++) {
    float* crow = C + (size_t)(m0 + ty * 8 + i) * 1024 + n0 + tx * 8;
    float4 v0, v1;
    v0.x = sigmoid_ref(acc[i][0]); v0.y = sigmoid_ref(acc[i][1]);
    v0.z = sigmoid_ref(acc[i][2]); v0.w = sigmoid_ref(acc[i][3]);
    v1.x = sigmoid_ref(acc[i][4]); v1.y = sigmoid_ref(acc[i][5]);
    v1.z = sigmoid_ref(acc[i][6]); v1.w = sigmoid_ref(acc[i][7]);
    *(float4*)(crow)     = v0;
    *(float4*)(crow + 4) = v1;
  }
}

// ---------------- software grid barrier (all NBLK blocks resident) ----------------
__device__ __forceinline__ void grid_sync(unsigned target) {
  __threadfence();            // release
  __syncthreads();
  if (threadIdx.x == 0) {
    atomicAdd(&g_bar, 1u);
    while (*(volatile unsigned*)&g_bar < target) { __nanosleep(64); }
    __threadfence();          // acquire
  }
  __syncthreads();
}

// ---------------- persistent recurrence kernel (ONE launch, 512 steps) -----------
// Phase 1: g_preHH = spike @ W_hh with SERIAL K per output (single accumulator,
//          k = 0..1023 strictly ascending) — matches cuBLAS/Eigen per-element order.
// Phase 2: fused epilogue: exp-form logistic (libdevice-exact), FMA-contracted
//          mul-adds (matching XLA:GPU codegen), threefry bernoulli.
__global__ __launch_bounds__(256) void recurrence_kernel(const float* __restrict__ W,
                                                         float* __restrict__ out) {
  const int blk = blockIdx.x;          // 0..127
  const int tid = threadIdx.x;

  // phase-1: 16 h-tiles (64 wide) x 8 b-tiles (8 tall); thread: 1 h, 2 b rows.
  const int h0  = (blk & 15) * 64;
  const int b0  = (blk >> 4) * 8;
  const int hl  = tid & 63;            // h-local 0..63
  const int bg2 = (tid >> 6) * 2;      // b-local 0,2,4,6

  // phase-2: 2 contiguous elements per thread
  const int gtid  = blk * 256 + tid;
  const int base2 = gtid * 2;

  __shared__ float WsT[64][33];        // [h-local][kk] transposed W chunk, pad 33
  __shared__ float Ss[8][32];          // [b-local][kk] spike chunk

  unsigned bar_target = 0;

  for (int t = 0; t < TSTEPS; t++) {
    // ---------- phase 1: serial-K GEMM ----------
    float acc0 = 0.0f, acc1 = 0.0f;

    for (int kc = 0; kc < 32; kc++) {          // 32 chunks of 32 k
      const int k0 = kc * 32;
      {
        // load W chunk [32 k][64 h] -> WsT[h][k]; 8 floats per thread
        int kk  = tid >> 3;
        int hh8 = (tid & 7) * 8;
        const float* src = W + (size_t)(k0 + kk) * HH + h0 + hh8;
        float4 wa = *(const float4*)(src);
        float4 wb = *(const float4*)(src + 4);
        WsT[hh8 + 0][kk] = wa.x; WsT[hh8 + 1][kk] = wa.y;
        WsT[hh8 + 2][kk] = wa.z; WsT[hh8 + 3][kk] = wa.w;
        WsT[hh8 + 4][kk] = wb.x; WsT[hh8 + 5][kk] = wb.y;
        WsT[hh8 + 6][kk] = wb.z; WsT[hh8 + 7][kk] = wb.w;
      }
      if (tid < 64) {
        // load spike chunk [8 b][32 k]; float4 per thread
        int b  = tid >> 3;
        int q4 = (tid & 7) * 4;
        float4 v = __ldcg((const float4*)(g_spike + (size_t)(b0 + b) * HH + k0 + q4));
        *(float4*)&Ss[b][q4] = v;
      }
      __syncthreads();

#pragma unroll
      for (int j = 0; j < 8; j++) {            // 8 sub-chunks of 4 k, k ascending
        float4 s0 = *(const float4*)&Ss[bg2][j * 4];       // broadcast
        float4 s1 = *(const float4*)&Ss[bg2 + 1][j * 4];   // broadcast
        float w0 = WsT[hl][j * 4 + 0];
        acc0 = __fmaf_rn(s0.x, w0, acc0);  acc1 = __fmaf_rn(s1.x, w0, acc1);
        float w1 = WsT[hl][j * 4 + 1];
        acc0 = __fmaf_rn(s0.y, w1, acc0);  acc1 = __fmaf_rn(s1.y, w1, acc1);
        float w2 = WsT[hl][j * 4 + 2];
        acc0 = __fmaf_rn(s0.z, w2, acc0);  acc1 = __fmaf_rn(s1.z, w2, acc1);
        float w3 = WsT[hl][j * 4 + 3];
        acc0 = __fmaf_rn(s0.w, w3, acc0);  acc1 = __fmaf_rn(s1.w, w3, acc1);
      }
      __syncthreads();
    }
    g_preHH[(size_t)(b0 + bg2) * HH + h0 + hl]     = acc0;
    g_preHH[(size_t)(b0 + bg2 + 1) * HH + h0 + hl] = acc1;

    bar_target += NBLK;
    grid_sync(bar_target);

    // ---------- phase 2: epilogue on 2 elements ----------
    {
      unsigned kk1, kk2;
      tf2x32(0u, 42u, 0u, (unsigned)t, kk1, kk2);   // key_t = fold-split of key(42)

      float2 hh2 = __ldcg((const float2*)(g_preHH + base2));
      float2 xw2 = *(const float2*)(g_preXW + (size_t)t * NBH + base2);
      float2 pp2 = __ldcg((const float2*)(g_prob + base2));
      const float hhv[2] = {hh2.x, hh2.y};
      const float xw[2]  = {xw2.x, xw2.y};
      const float pp[2]  = {pp2.x, pp2.y};

      float probv[2], spikev[2];
#pragma unroll
      for (int j = 0; j < 2; j++) {
        float pre  = __fadd_rn(xw[j], hhv[j]);    // dot_ih + dot_hh
        // XLA: add(mul(0.9, prob_prev), mul(0.1, pre)) -> contracted:
        //      fma(0.9, prob_prev, mul(0.1, pre))
        float l    = __fmaf_rn(0.9f, pp[j], __fmul_rn(0.1f, pre));
        float s    = sigmoid_ref(l);
        // XLA: add(mul(0.99, s), 0.005) -> contracted: fma(0.99, s, 0.005)
        float prob = __fmaf_rn(0.99f, s, 0.005f);
        unsigned o0, o1;
        tf2x32(kk1, kk2, 0u, (unsigned)(base2 + j), o0, o1);
        unsigned bits = o0 ^ o1;
        float u    = __fsub_rn(__uint_as_float((bits >> 9) | 0x3f800000u), 1.0f);
        u = fmaxf(0.0f, u);                       // jax uniform: max(minval, u)
        float samp = (u < prob) ? 1.0f : 0.0f;
        float spike = __fsub_rn(__fadd_rn(samp, prob), prob);  // straight-through fwd
        probv[j] = prob; spikev[j] = spike;
      }

      float2 pv = make_float2(probv[0], probv[1]);
      float2 sv = make_float2(spikev[0], spikev[1]);
      *(float2*)(g_prob + base2)  = pv;
      *(float2*)(g_spike + base2) = sv;
      *(float2*)(out + OFF_PROBS + (size_t)t * NBH + base2) = pv;
      *(float2*)(out + OFF_SPIKES + (size_t)(t + 1) * NBH + base2) = sv;
      if (t == TSTEPS - 1) {
        *(float2*)(out + OFF_PROBT + base2)  = pv;
        *(float2*)(out + OFF_SPIKET + base2) = sv;
      }
    }

    bar_target += NBLK;
    grid_sync(bar_target);
  }
}

// ---------------- launch: 4 graph nodes total ----------------
extern "C" void kernel_launch(void* const* d_in, const int* in_sizes, int n_in,
                              void* d_out, int out_size) {
  (void)in_sizes; (void)n_in; (void)out_size;
  const float* X    = (const float*)d_in[0];   // [512,64,1024]
  const float* W_ih = (const float*)d_in[1];   // [1024,1024]
  const float* W_hh = (const float*)d_in[2];   // [1024,1024]
  float* out = (float*)d_out;

  init_kernel<<<NBH / 256, 256>>>(out);

  {
    dim3 g(HH / 128, (TSTEPS * BB) / 128);     // (8, 256)
    sgemm_xw<<<g, 256>>>(X, W_ih);
  }

  recurrence_kernel<<<NBLK, 256>>>(W_hh, out);

  {
    dim3 g(HH / 128, (TSTEPS * BB) / 128);
    sgemm_pred<<<g, 256>>>(out + OFF_PROBS, W_hh, out + OFF_PREDS);
  }
}

// round 17
// speedup vs baseline: 1.1759x; 1.1759x over previous
#include <cuda_runtime.h>
#include <cstdint>
#include <math.h>

// Problem shape (fixed): T=512, B=64, I=H=1024.
#define TSTEPS 512
#define BB     64
#define HH     1024
#define NBH    65536   // B*H
#define NBLK   128     // persistent-kernel blocks (<=148 SMs -> all resident)

typedef unsigned long long u64;

// ---------------- output layout (floats) ----------------
static const size_t OFF_SPIKES = 0;
static const size_t OFF_PREDS  = (size_t)513 * NBH;
static const size_t OFF_PROBS  = OFF_PREDS + (size_t)TSTEPS * NBH;
static const size_t OFF_PROBT  = OFF_PROBS + (size_t)TSTEPS * NBH;
static const size_t OFF_SPIKET = OFF_PROBT + NBH;

// ---------------- device scratch (static: no allocation) ----------------
static __device__ float g_preXW[(size_t)TSTEPS * NBH];   // 128 MB: x_t @ W_ih
static __device__ u64   g_spike_pair[32 * HH];           // (spike[2p][h], spike[2p+1][h])
static __device__ u64   g_preHH_pair[32 * HH];           // (preHH[2p][h], preHH[2p+1][h])
static __device__ unsigned g_bar;

// ---------------- f32x2 packed helpers ----------------
__device__ __forceinline__ u64 pack2(float lo, float hi) {
  u64 r; asm("mov.b64 %0, {%1, %2};" : "=l"(r) : "f"(lo), "f"(hi)); return r;
}
__device__ __forceinline__ void unpack2(u64 v, float& lo, float& hi) {
  asm("mov.b64 {%0, %1}, %2;" : "=f"(lo), "=f"(hi) : "l"(v));
}
__device__ __forceinline__ void ffma2(u64& d, u64 a, u64 b) {
  asm("fma.rn.f32x2 %0, %1, %2, %0;" : "+l"(d) : "l"(a), "l"(b));
}

// ---------------- threefry2x32 (JAX-exact, 20 rounds) ----------------
__host__ __device__ inline void tf2x32(unsigned k0, unsigned k1,
                                       unsigned x0, unsigned x1,
                                       unsigned& o0, unsigned& o1) {
  unsigned ks2 = k0 ^ k1 ^ 0x1BD11BDAu;
  x0 += k0; x1 += k1;
#define TFR(r) { x0 += x1; x1 = (x1 << (r)) | (x1 >> (32 - (r))); x1 ^= x0; }
  TFR(13) TFR(15) TFR(26) TFR(6)
  x0 += k1;  x1 += ks2 + 1u;
  TFR(17) TFR(29) TFR(16) TFR(24)
  x0 += ks2; x1 += k0 + 2u;
  TFR(13) TFR(15) TFR(26) TFR(6)
  x0 += k0;  x1 += k1 + 3u;
  TFR(17) TFR(29) TFR(16) TFR(24)
  x0 += k1;  x1 += ks2 + 4u;
  TFR(13) TFR(15) TFR(26) TFR(6)
  x0 += ks2; x1 += k0 + 5u;
#undef TFR
  o0 = x0; o1 = x1;
}

// ---------------- bit-faithful replica of libdevice __nv_expf ----------------
__device__ inline float expf_ref(float a) {
  float j = __fadd_rn(__fmaf_rn(a, 1.442695f, 12582912.0f), -12582912.0f);
  int   i = (int)j;
  float f = __fmaf_rn(j, -6.93145752e-1f, a);
  f = __fmaf_rn(j, -1.42860677e-6f, f);
  float r =                 1.37805939e-3f;
  r = __fmaf_rn(r, f, 8.37312452e-3f);
  r = __fmaf_rn(r, f, 4.16695364e-2f);
  r = __fmaf_rn(r, f, 1.66664720e-1f);
  r = __fmaf_rn(r, f, 4.99999851e-1f);
  r = __fmaf_rn(r, f, 1.00000000e+0f);
  r = __fmaf_rn(r, f, 1.00000000e+0f);
  int ih = i / 2;
  r = __fmul_rn(r, __int_as_float((unsigned)(ih + 127) << 23));
  r = __fmul_rn(r, __int_as_float((unsigned)(i - ih + 127) << 23));
  return r;
}
__device__ inline float sigmoid_ref(float x) {
  float e = expf_ref(-x);
  return __fdiv_rn(1.0f, __fadd_rn(1.0f, e));
}

// ---------------- init ----------------
__global__ __launch_bounds__(256) void init_kernel(float* __restrict__ out) {
  int i = blockIdx.x * 256 + threadIdx.x;   // 65536 threads
  out[OFF_SPIKES + i] = 0.0f;               // spikes[0] = 0
  if (i < 32 * HH) g_spike_pair[i] = 0ull;
  if (i == 0) g_bar = 0u;
}

// ---------------- big SGEMM: g_preXW = X @ W_ih  (BK=16, FFMA2) -------------
__global__ __launch_bounds__(256, 2) void sgemm_xw(const float* __restrict__ A,
                                                   const float* __restrict__ B) {
  const int n0 = blockIdx.x * 128;
  const int m0 = blockIdx.y * 128;
  __shared__ float As[16][128];
  __shared__ float Bs[16][128];
  const int tid = threadIdx.x;
  const int tx = tid & 15, ty = tid >> 4;
  const int ar = tid >> 1, akq = (tid & 1) * 8;     // A staging
  const int brk = tid >> 4, bc = (tid & 15) * 8;    // B staging

  u64 acc2[4][8];
#pragma unroll
  for (int p = 0; p < 4; p++)
#pragma unroll
    for (int j = 0; j < 8; j++) acc2[p][j] = 0ull;

  float4 pa0 = *(const float4*)(A + (size_t)(m0 + ar) * 1024 + akq);
  float4 pa1 = *(const float4*)(A + (size_t)(m0 + ar) * 1024 + akq + 4);
  float4 pb0 = *(const float4*)(B + (size_t)brk * 1024 + n0 + bc);
  float4 pb1 = *(const float4*)(B + (size_t)brk * 1024 + n0 + bc + 4);

  for (int k0 = 0; k0 < 1024; k0 += 16) {
    As[akq + 0][ar] = pa0.x; As[akq + 1][ar] = pa0.y;
    As[akq + 2][ar] = pa0.z; As[akq + 3][ar] = pa0.w;
    As[akq + 4][ar] = pa1.x; As[akq + 5][ar] = pa1.y;
    As[akq + 6][ar] = pa1.z; As[akq + 7][ar] = pa1.w;
    *(float4*)&Bs[brk][bc]     = pb0;
    *(float4*)&Bs[brk][bc + 4] = pb1;
    __syncthreads();
    if (k0 + 16 < 1024) {
      pa0 = *(const float4*)(A + (size_t)(m0 + ar) * 1024 + k0 + 16 + akq);
      pa1 = *(const float4*)(A + (size_t)(m0 + ar) * 1024 + k0 + 16 + akq + 4);
      pb0 = *(const float4*)(B + (size_t)(k0 + 16 + brk) * 1024 + n0 + bc);
      pb1 = *(const float4*)(B + (size_t)(k0 + 16 + brk) * 1024 + n0 + bc + 4);
    }
#pragma unroll
    for (int kk = 0; kk < 16; kk++) {
      const u64* ap = reinterpret_cast<const u64*>(&As[kk][ty * 8]);
      u64 a0 = ap[0], a1 = ap[1], a2 = ap[2], a3 = ap[3];
      float bv[8];
      *(float4*)&bv[0] = *(const float4*)&Bs[kk][tx * 8];
      *(float4*)&bv[4] = *(const float4*)&Bs[kk][tx * 8 + 4];
#pragma unroll
      for (int j = 0; j < 8; j++) {
        u64 b2 = pack2(bv[j], bv[j]);
        ffma2(acc2[0][j], a0, b2);
        ffma2(acc2[1][j], a1, b2);
        ffma2(acc2[2][j], a2, b2);
        ffma2(acc2[3][j], a3, b2);
      }
    }
    __syncthreads();
  }
#pragma unroll
  for (int p = 0; p < 4; p++) {
    float r0[8], r1[8];
#pragma unroll
    for (int j = 0; j < 8; j++) unpack2(acc2[p][j], r0[j], r1[j]);
    float* c0 = g_preXW + (size_t)(m0 + ty * 8 + 2 * p) * 1024 + n0 + tx * 8;
    float* c1 = c0 + 1024;
    *(float4*)(c0)     = make_float4(r0[0], r0[1], r0[2], r0[3]);
    *(float4*)(c0 + 4) = make_float4(r0[4], r0[5], r0[6], r0[7]);
    *(float4*)(c1)     = make_float4(r1[0], r1[1], r1[2], r1[3]);
    *(float4*)(c1 + 4) = make_float4(r1[4], r1[5], r1[6], r1[7]);
  }
}

// ---------------- big SGEMM: preds = sigmoid_ref(probs @ W_hh^T) -------------
__global__ __launch_bounds__(256, 2) void sgemm_pred(const float* __restrict__ A,
                                                     const float* __restrict__ W,
                                                     float* __restrict__ C) {
  const int n0 = blockIdx.x * 128;
  const int m0 = blockIdx.y * 128;
  __shared__ float As[16][128];
  __shared__ float Bs[16][128];
  const int tid = threadIdx.x;
  const int tx = tid & 15, ty = tid >> 4;
  const int ar = tid >> 1, akq = (tid & 1) * 8;     // A staging
  const int br = tid & 127, bkq = (tid >> 7) * 8;   // B staging (transposed)

  u64 acc2[4][8];
#pragma unroll
  for (int p = 0; p < 4; p++)
#pragma unroll
    for (int j = 0; j < 8; j++) acc2[p][j] = 0ull;

  float4 pa0 = *(const float4*)(A + (size_t)(m0 + ar) * 1024 + akq);
  float4 pa1 = *(const float4*)(A + (size_t)(m0 + ar) * 1024 + akq + 4);
  float4 pb0 = *(const float4*)(W + (size_t)(n0 + br) * 1024 + bkq);
  float4 pb1 = *(const float4*)(W + (size_t)(n0 + br) * 1024 + bkq + 4);

  for (int k0 = 0; k0 < 1024; k0 += 16) {
    As[akq + 0][ar] = pa0.x; As[akq + 1][ar] = pa0.y;
    As[akq + 2][ar] = pa0.z; As[akq + 3][ar] = pa0.w;
    As[akq + 4][ar] = pa1.x; As[akq + 5][ar] = pa1.y;
    As[akq + 6][ar] = pa1.z; As[akq + 7][ar] = pa1.w;
    Bs[bkq + 0][br] = pb0.x; Bs[bkq + 1][br] = pb0.y;
    Bs[bkq + 2][br] = pb0.z; Bs[bkq + 3][br] = pb0.w;
    Bs[bkq + 4][br] = pb1.x; Bs[bkq + 5][br] = pb1.y;
    Bs[bkq + 6][br] = pb1.z; Bs[bkq + 7][br] = pb1.w;
    __syncthreads();
    if (k0 + 16 < 1024) {
      pa0 = *(const float4*)(A + (size_t)(m0 + ar) * 1024 + k0 + 16 + akq);
      pa1 = *(const float4*)(A + (size_t)(m0 + ar) * 1024 + k0 + 16 + akq + 4);
      pb0 = *(const float4*)(W + (size_t)(n0 + br) * 1024 + k0 + 16 + bkq);
      pb1 = *(const float4*)(W + (size_t)(n0 + br) * 1024 + k0 + 16 + bkq + 4);
    }
#pragma unroll
    for (int kk = 0; kk < 16; kk++) {
      const u64* ap = reinterpret_cast<const u64*>(&As[kk][ty * 8]);
      u64 a0 = ap[0], a1 = ap[1], a2 = ap[2], a3 = ap[3];
      float bv[8];
      *(float4*)&bv[0] = *(const float4*)&Bs[kk][tx * 8];
      *(float4*)&bv[4] = *(const float4*)&Bs[kk][tx * 8 + 4];
#pragma unroll
      for (int j = 0; j < 8; j++) {
        u64 b2 = pack2(bv[j], bv[j]);
        ffma2(acc2[0][j], a0, b2);
        ffma2(acc2[1][j], a1, b2);
        ffma2(acc2[2][j], a2, b2);
        ffma2(acc2[3][j], a3, b2);
      }
    }
    __syncthreads();
  }
#pragma unroll
  for (int p = 0; p < 4; p++) {
    float r0[8], r1[8];
#pragma unroll
    for (int j = 0; j < 8; j++) unpack2(acc2[p][j], r0[j], r1[j]);
    float* c0 = C + (size_t)(m0 + ty * 8 + 2 * p) * 1024 + n0 + tx * 8;
    float* c1 = c0 + 1024;
    float4 v;
    v = make_float4(sigmoid_ref(r0[0]), sigmoid_ref(r0[1]), sigmoid_ref(r0[2]), sigmoid_ref(r0[3]));
    *(float4*)(c0) = v;
    v = make_float4(sigmoid_ref(r0[4]), sigmoid_ref(r0[5]), sigmoid_ref(r0[6]), sigmoid_ref(r0[7]));
    *(float4*)(c0 + 4) = v;
    v = make_float4(sigmoid_ref(r1[0]), sigmoid_ref(r1[1]), sigmoid_ref(r1[2]), sigmoid_ref(r1[3]));
    *(float4*)(c1) = v;
    v = make_float4(sigmoid_ref(r1[4]), sigmoid_ref(r1[5]), sigmoid_ref(r1[6]), sigmoid_ref(r1[7]));
    *(float4*)(c1 + 4) = v;
  }
}

// ---------------- software grid barrier ----------------
__device__ __forceinline__ void grid_sync(unsigned target) {
  __threadfence();
  __syncthreads();
  if (threadIdx.x == 0) {
    atomicAdd(&g_bar, 1u);
    while (*(volatile unsigned*)&g_bar < target) { __nanosleep(64); }
    __threadfence();
  }
  __syncthreads();
}

// ---------------- persistent recurrence kernel (ONE launch, 512 steps) -------
// Phase 1: preHH = spike @ W_hh, serial ascending K per output, FFMA2 packed
//          over the b-pair. w: LDS.32 (128B/warp, crossbar-minimal); spikes:
//          smem-staged pre-packed u64 pairs, warp-uniform broadcast reads.
// Phase 2: epilogue math verbatim from R13; prob carry lives in registers.
__global__ __launch_bounds__(256) void recurrence_kernel(const float* __restrict__ W,
                                                         float* __restrict__ out) {
  const int blk = blockIdx.x;          // 0..127
  const int tid = threadIdx.x;

  // phase-1 assignment: 16 h-tiles(64) x 8 bp-tiles(4 b-pairs = 8 b)
  const int h0  = (blk & 15) * 64;
  const int bp0 = (blk >> 4) * 4;
  const int hl  = tid & 63;            // h-local 0..63
  const int bpl = tid >> 6;            // 0..3 (warp-uniform)
  const int bp  = bp0 + bpl;

  // phase-2 assignment: (b-pair, h)
  const int gtid = blk * 256 + tid;    // 0..32767
  const int bp2  = gtid >> 10;         // 0..31
  const int h2   = gtid & 1023;

  __shared__ float Ws[32][64];         // current W chunk [k][h]     (8 KB)
  __shared__ u64   Sp[4][HH];          // spike pairs for 4 bp       (32 KB)

  const int skk = tid >> 3, sh8 = (tid & 7) * 8;   // W staging coords

  unsigned bar_target = 0;
  float pp0 = 0.0f, pp1 = 0.0f;        // prob carry (this thread's 2 elements)

  // prefetch W chunk 0
  float4 w0 = *(const float4*)(W + (size_t)skk * HH + h0 + sh8);
  float4 w1 = *(const float4*)(W + (size_t)skk * HH + h0 + sh8 + 4);

  for (int t = 0; t < TSTEPS; t++) {
    // ---- stage spike pairs for this block's 4 bp (4096 u64) ----
    {
      const longlong2* src = (const longlong2*)(g_spike_pair + (size_t)bp0 * HH);
      longlong2* dst = (longlong2*)&Sp[0][0];
#pragma unroll
      for (int i = 0; i < 8; i++)
        dst[tid + i * 256] = __ldcg(src + tid + i * 256);
    }

    // ---- phase 1: serial-K GEMM (k = 0..1023 ascending per output) ----
    u64 acc2 = 0ull;
    for (int kc = 0; kc < 32; kc++) {
      __syncthreads();                 // previous chunk fully consumed (+ Sp staged)
      *(float4*)&Ws[skk][sh8]     = w0;
      *(float4*)&Ws[skk][sh8 + 4] = w1;
      __syncthreads();
      {
        const int nkc = (kc == 31) ? 0 : kc + 1;   // prefetch next (or next step's 0)
        w0 = *(const float4*)(W + (size_t)(nkc * 32 + skk) * HH + h0 + sh8);
        w1 = *(const float4*)(W + (size_t)(nkc * 32 + skk) * HH + h0 + sh8 + 4);
      }
      const int kb = kc * 32;
#pragma unroll
      for (int kk = 0; kk < 32; kk += 2) {
        longlong2 sv = *(const longlong2*)&Sp[bpl][kb + kk];  // uniform broadcast
        float wa = Ws[kk][hl];
        ffma2(acc2, pack2(wa, wa), (u64)sv.x);
        float wb = Ws[kk + 1][hl];
        ffma2(acc2, pack2(wb, wb), (u64)sv.y);
      }
    }
    g_preHH_pair[(size_t)bp * HH + h0 + hl] = acc2;

    bar_target += NBLK;
    grid_sync(bar_target);

    // ---- phase 2: epilogue on elements (2*bp2, h2) and (2*bp2+1, h2) ----
    {
      unsigned kk1, kk2;
      tf2x32(0u, 42u, 0u, (unsigned)t, kk1, kk2);   // key_t = fold-split of key(42)

      u64 hhp = __ldcg(g_preHH_pair + (size_t)bp2 * HH + h2);
      float hh0, hh1; unpack2(hhp, hh0, hh1);
      const size_t rowA = (size_t)(bp2 * 2) * HH + h2;   // flat idx of (b=2bp2, h2)
      float xw0 = g_preXW[(size_t)t * NBH + rowA];
      float xw1 = g_preXW[(size_t)t * NBH + rowA + HH];

      const float hhv[2] = {hh0, hh1};
      const float xw[2]  = {xw0, xw1};
      const float ppv[2] = {pp0, pp1};
      float probv[2], spikev[2];
#pragma unroll
      for (int j = 0; j < 2; j++) {
        float pre  = __fadd_rn(xw[j], hhv[j]);
        float l    = __fmaf_rn(0.9f, ppv[j], __fmul_rn(0.1f, pre));
        float s    = sigmoid_ref(l);
        float prob = __fmaf_rn(0.99f, s, 0.005f);
        unsigned o0, o1;
        tf2x32(kk1, kk2, 0u, (unsigned)(rowA + (size_t)j * HH), o0, o1);
        unsigned bits = o0 ^ o1;
        float u    = __fsub_rn(__uint_as_float((bits >> 9) | 0x3f800000u), 1.0f);
        u = fmaxf(0.0f, u);
        float samp = (u < prob) ? 1.0f : 0.0f;
        float spike = __fsub_rn(__fadd_rn(samp, prob), prob);  // straight-through
        probv[j] = prob; spikev[j] = spike;
      }
      pp0 = probv[0]; pp1 = probv[1];

      out[OFF_PROBS + (size_t)t * NBH + rowA]        = probv[0];
      out[OFF_PROBS + (size_t)t * NBH + rowA + HH]   = probv[1];
      out[OFF_SPIKES + (size_t)(t + 1) * NBH + rowA]      = spikev[0];
      out[OFF_SPIKES + (size_t)(t + 1) * NBH + rowA + HH] = spikev[1];
      g_spike_pair[(size_t)bp2 * HH + h2] = pack2(spikev[0], spikev[1]);
      if (t == TSTEPS - 1) {
        out[OFF_PROBT + rowA]       = probv[0];
        out[OFF_PROBT + rowA + HH]  = probv[1];
        out[OFF_SPIKET + rowA]      = spikev[0];
        out[OFF_SPIKET + rowA + HH] = spikev[1];
      }
    }

    bar_target += NBLK;
    grid_sync(bar_target);
  }
}

// ---------------- launch: 4 graph nodes ----------------
extern "C" void kernel_launch(void* const* d_in, const int* in_sizes, int n_in,
                              void* d_out, int out_size) {
  (void)in_sizes; (void)n_in; (void)out_size;
  const float* X    = (const float*)d_in[0];   // [512,64,1024]
  const float* W_ih = (const float*)d_in[1];   // [1024,1024]
  const float* W_hh = (const float*)d_in[2];   // [1024,1024]
  float* out = (float*)d_out;

  init_kernel<<<NBH / 256, 256>>>(out);

  {
    dim3 g(HH / 128, (TSTEPS * BB) / 128);     // (8, 256)
    sgemm_xw<<<g, 256>>>(X, W_ih);
  }

  recurrence_kernel<<<NBLK, 256>>>(W_hh, out);

  {
    dim3 g(HH / 128, (TSTEPS * BB) / 128);
    sgemm_pred<<<g, 256>>>(out + OFF_PROBS, W_hh, out + OFF_PREDS);
  }
}